// round 7
// baseline (speedup 1.0000x reference)
#include <cuda_runtime.h>
#include <cuda_fp16.h>
#include <cstdint>
#include <cstddef>

#define CHANS 256
#define HWSZ  3136
#define BATCH 32
#define NPOS  (BATCH*HWSZ)        // 100352
#define STEPS 10
#define SCOPE 15
#define PADC  7

#define TILE_P 128                // positions per CTA
#define TILE_C 256                // ALL output channels per CTA (X staged once)
#define KC     32                 // cin per chunk
#define NCHUNK (CHANS/KC)         // 8
#define XSTR   136                // u32 stride: %32==8 -> 8q+g bank permutation
#define WSTR   264                // u32 stride: %32==8 -> same permutation
#define XBUF   (16*XSTR)          // per-buffer u32 (16 k2-rows x 128 pos)
#define WBUF   (16*WSTR)          // per-buffer u32 (16 k2-rows x 256 cout)
#define SMEM_BYTES ((2*XBUF + 2*WBUF)*4)   // 51200 B

// W_eff = sum_{k=0..10} T^k, fp16: g_wh[cin][cout]
__device__ __half g_wh[CHANS*CHANS];

// ---------------- helpers ----------------
__device__ __forceinline__ uint32_t pkh2(float hi, float lo){
    uint32_t r; asm("cvt.rn.f16x2.f32 %0, %1, %2;" : "=r"(r) : "f"(hi), "f"(lo)); return r;
}
__device__ __forceinline__ uint32_t prmt(uint32_t a, uint32_t b, uint32_t sel){
    uint32_t r; asm("prmt.b32 %0, %1, %2, %3;" : "=r"(r) : "r"(a), "r"(b), "r"(sel)); return r;
}
__device__ __forceinline__ void mma16(float* d, const uint32_t* a, uint32_t b0, uint32_t b1){
    asm volatile("mma.sync.aligned.m16n8k16.row.col.f32.f16.f16.f32 "
        "{%0,%1,%2,%3}, {%4,%5,%6,%7}, {%8,%9}, {%0,%1,%2,%3};"
        : "+f"(d[0]), "+f"(d[1]), "+f"(d[2]), "+f"(d[3])
        : "r"(a[0]), "r"(a[1]), "r"(a[2]), "r"(a[3]), "r"(b0), "r"(b1));
}

// ---------------- Kernel 1: build W_eff (fp16) ----------------
// Block j: column j of S = sum_{k=0..STEPS} T^k via S_{s+1} = I + T*S_s (exact,
// includes zero-pad boundaries). Thread i holds S[i][j] = W[cout=i][cin=j];
// writes g_wh[cin=j][cout=i] (coalesced).
__global__ void build_weff_kernel(const float* __restrict__ w){
    __shared__ float sv[CHANS + 2*PADC];
    const int i = threadIdx.x, j = blockIdx.x;
    if (i < PADC){ sv[i] = 0.f; sv[CHANS + PADC + i] = 0.f; }
    float wv[SCOPE];
#pragma unroll
    for (int k = 0; k < SCOPE; ++k) wv[k] = w[k];
    float v = (i == j) ? 1.f : 0.f;
    for (int s = 0; s < STEPS; ++s){
        __syncthreads();
        sv[PADC + i] = v;
        __syncthreads();
        float acc = (i == j) ? 1.f : 0.f;
#pragma unroll
        for (int k = 0; k < SCOPE; ++k) acc = fmaf(wv[k], sv[i + k], acc);
        v = acc;
    }
    g_wh[j * CHANS + i] = __float2half_rn(v);
}

// ---------------- Kernel 2: out = W_eff * X via fp16 mma.sync ----------------
// One CTA = 128 pos x ALL 256 couts (X staged exactly once). 512 threads,
// 16 warps: wp=wid>>2 pos quarter, wc=wid&3 cout quarter; warp tile 32x64.
// Both operands in SMEM as k-paired fp16 u32 {v(2k),v(2k+1)} at [k2][col]:
// every mma fragment register = one conflict-free LDS.32.
__global__ void __launch_bounds__(512, 1)
gemm_kernel(const float* __restrict__ x, float* __restrict__ out){
    extern __shared__ uint32_t smu[];
    uint32_t* xbuf = smu;              // 2 x [16][XSTR]
    uint32_t* wbuf = smu + 2*XBUF;     // 2 x [16][WSTR]

    const int tid  = threadIdx.x;
    const int lane = tid & 31;
    const int wid  = tid >> 5;
    const int g = lane >> 2, q = lane & 3;
    const int wp = wid >> 2, wc = wid & 3;
    const int tile = blockIdx.x;       // 0..783

    // X staging: thread -> (k2 row = wid, 4 consecutive pos)
    const int sk2 = tid >> 5;              // 0..15
    const int sp0 = (tid & 31) << 2;       // 0,4,...,124
    const int sn  = tile * TILE_P + sp0;   // 4|3136 -> never straddles batch
    const int sb  = sn / HWSZ;
    const int spp = sn - sb * HWSZ;
    const float* xsrc = x + ((size_t)sb * CHANS + 2 * sk2) * HWSZ + spp;

    float4 xf0, xf1;
    auto ldg_x = [&](int kc){
        const float* s0 = xsrc + (size_t)(kc * KC) * HWSZ;
        xf0 = *(const float4*)s0;
        xf1 = *(const float4*)(s0 + HWSZ);
    };
    auto sts_x = [&](uint32_t* buf){
        uint4 v;
        v.x = pkh2(xf1.x, xf0.x);  v.y = pkh2(xf1.y, xf0.y);
        v.z = pkh2(xf1.z, xf0.z);  v.w = pkh2(xf1.w, xf0.w);
        *(uint4*)(buf + sk2 * XSTR + sp0) = v;
    };
    // W staging: 2048 uint2 (16 k2 x 128 cout-pairs), 4 per thread (L2-hot)
    auto stage_w = [&](int kc, uint32_t* buf){
#pragma unroll
        for (int i = 0; i < 4; ++i){
            int id  = tid + i * 512;            // 0..2047
            int k2l = id >> 7;                  // 0..15
            int n2  = (id & 127) << 1;          // 0..254
            const __half* r0 = g_wh + (size_t)(kc * KC + 2 * k2l) * CHANS + n2;
            uint32_t a = *(const uint32_t*)r0;
            uint32_t b = *(const uint32_t*)(r0 + CHANS);
            *(uint2*)(buf + k2l * WSTR + n2) =
                make_uint2(prmt(a, b, 0x5410), prmt(a, b, 0x7632));
        }
    };

    float acc[2][8][4];
#pragma unroll
    for (int mt = 0; mt < 2; ++mt)
#pragma unroll
        for (int nt = 0; nt < 8; ++nt)
#pragma unroll
            for (int r = 0; r < 4; ++r) acc[mt][nt][r] = 0.f;

    // prologue: chunk0 into smem, chunk1 X into regs
    ldg_x(0);
    stage_w(0, wbuf);
    sts_x(xbuf);
    stage_w(1, wbuf + WBUF);
    ldg_x(1);
    __syncthreads();

    for (int c = 0; c < NCHUNK; ++c){
        const uint32_t* xb = xbuf + (c & 1) * XBUF;
        const uint32_t* wb = wbuf + (c & 1) * WBUF;
#pragma unroll
        for (int ks = 0; ks < 2; ++ks){
            const uint32_t* xk = xb + (ks * 8 + q) * XSTR + wp * 32;
            uint32_t a[2][4];
#pragma unroll
            for (int mt = 0; mt < 2; ++mt){
                int p0 = mt * 16 + g;
                a[mt][0] = xk[p0];
                a[mt][1] = xk[p0 + 8];
                a[mt][2] = xk[4 * XSTR + p0];
                a[mt][3] = xk[4 * XSTR + p0 + 8];
            }
            const uint32_t* wk = wb + (ks * 8 + q) * WSTR + wc * 64 + g;
#pragma unroll
            for (int nt = 0; nt < 8; ++nt){
                uint32_t b0 = wk[nt * 8];
                uint32_t b1 = wk[4 * WSTR + nt * 8];
                mma16(acc[0][nt], a[0], b0, b1);
                mma16(acc[1][nt], a[1], b0, b1);
            }
        }
        if (c < NCHUNK - 1){
            // single-sync safety: writes to buffer (c+1)&1 happen only after the
            // end-of-(c-1) barrier, by which all warps finished reading chunk c-1.
            sts_x(xbuf + ((c + 1) & 1) * XBUF);
            stage_w(c + 1, wbuf + ((c + 1) & 1) * WBUF);
            if (c < NCHUNK - 2) ldg_x(c + 2);
            __syncthreads();
        }
    }

    // epilogue: frag rows g|g+8 (pos), cols 2q,2q+1 (cout) -> out[cout][b,p]
#pragma unroll
    for (int mt = 0; mt < 2; ++mt){
#pragma unroll
        for (int rs = 0; rs < 2; ++rs){
            int pos = tile * TILE_P + wp * 32 + mt * 16 + g + rs * 8;
            int b = pos / HWSZ, p = pos - b * HWSZ;
            float* ob = out + ((size_t)b * CHANS + (size_t)(wc * 64 + 2 * q)) * HWSZ + p;
#pragma unroll
            for (int nt = 0; nt < 8; ++nt){
                ob[(size_t)(nt * 8) * HWSZ]     = acc[mt][nt][rs * 2 + 0];
                ob[(size_t)(nt * 8 + 1) * HWSZ] = acc[mt][nt][rs * 2 + 1];
            }
        }
    }
}

// ---------------- launch ----------------
extern "C" void kernel_launch(void* const* d_in, const int* in_sizes, int n_in,
                              void* d_out, int out_size)
{
    const float* acts = (const float*)d_in[0];
    const float* wrec = (const float*)d_in[1];
    float* out        = (float*)d_out;
    (void)in_sizes; (void)n_in; (void)out_size;

    cudaFuncSetAttribute(gemm_kernel, cudaFuncAttributeMaxDynamicSharedMemorySize, SMEM_BYTES);

    build_weff_kernel<<<CHANS, CHANS>>>(wrec);
    gemm_kernel<<<NPOS / TILE_P, 512, SMEM_BYTES>>>(acts, out);
}

// round 8
// speedup vs baseline: 1.1391x; 1.1391x over previous
#include <cuda_runtime.h>
#include <cuda_fp16.h>
#include <cstdint>
#include <cstddef>

#define CHANS 256
#define HWSZ  3136
#define BATCH 32
#define NPOS  (BATCH*HWSZ)        // 100352
#define STEPS 10
#define SCOPE 15
#define PADC  7

#define TILE_P 128                // positions per tile
#define KC     32                 // cin per chunk
#define NCHUNK (CHANS/KC)         // 8
#define NTILES (NPOS/TILE_P)      // 784
#define NSM    148                // persistent grid (safe on 148- or 152-SM parts)

#define XSTR   136                // u32 stride: %32==8 -> 8q+g bank permutation
#define WSTR   264                // u32 stride: %32==8 -> same permutation
#define XBUF   (16*XSTR)          // 2176 u32 per X buffer (16 k2-rows x 128 pos)
#define WRES   (128*WSTR)         // 33792 u32 resident W (128 k2-rows x 256 cout)
#define SMEM_BYTES ((2*XBUF + WRES)*4)   // 152576 B (<227KB)

// W_eff = sum_{k=0..10} T^k, fp16: g_wh[cin][cout]
__device__ __half g_wh[CHANS*CHANS];

// ---------------- helpers ----------------
__device__ __forceinline__ uint32_t pkh2(float hi, float lo){
    uint32_t r; asm("cvt.rn.f16x2.f32 %0, %1, %2;" : "=r"(r) : "f"(hi), "f"(lo)); return r;
}
__device__ __forceinline__ uint32_t prmt(uint32_t a, uint32_t b, uint32_t sel){
    uint32_t r; asm("prmt.b32 %0, %1, %2, %3;" : "=r"(r) : "r"(a), "r"(b), "r"(sel)); return r;
}
__device__ __forceinline__ void mma16(float* d, const uint32_t* a, uint32_t b0, uint32_t b1){
    asm volatile("mma.sync.aligned.m16n8k16.row.col.f32.f16.f16.f32 "
        "{%0,%1,%2,%3}, {%4,%5,%6,%7}, {%8,%9}, {%0,%1,%2,%3};"
        : "+f"(d[0]), "+f"(d[1]), "+f"(d[2]), "+f"(d[3])
        : "r"(a[0]), "r"(a[1]), "r"(a[2]), "r"(a[3]), "r"(b0), "r"(b1));
}

// ---------------- Kernel 1: build W_eff (fp16) ----------------
// Block j: column j of S = sum_{k=0..STEPS} T^k via S_{s+1} = I + T*S_s (exact,
// includes zero-pad boundaries). Thread i holds S[i][j] = W[cout=i][cin=j];
// writes g_wh[cin=j][cout=i] (coalesced).
__global__ void build_weff_kernel(const float* __restrict__ w){
    __shared__ float sv[CHANS + 2*PADC];
    const int i = threadIdx.x, j = blockIdx.x;
    if (i < PADC){ sv[i] = 0.f; sv[CHANS + PADC + i] = 0.f; }
    float wv[SCOPE];
#pragma unroll
    for (int k = 0; k < SCOPE; ++k) wv[k] = w[k];
    float v = (i == j) ? 1.f : 0.f;
    for (int s = 0; s < STEPS; ++s){
        __syncthreads();
        sv[PADC + i] = v;
        __syncthreads();
        float acc = (i == j) ? 1.f : 0.f;
#pragma unroll
        for (int k = 0; k < SCOPE; ++k) acc = fmaf(wv[k], sv[i + k], acc);
        v = acc;
    }
    g_wh[j * CHANS + i] = __float2half_rn(v);
}

// ---------------- Kernel 2: persistent GEMM out = W_eff * X ----------------
// 148 persistent CTAs, 512 threads. W (all 256x256, fp16 k-paired) resident in
// SMEM for the whole kernel; each CTA loops over tiles bid, bid+148, ...
// X staged per chunk via LDG.128 -> cvt.f16x2 -> STS.128, 2-deep pipeline that
// rolls across tile boundaries; one barrier per chunk. Every mma fragment
// register = one conflict-free LDS.32.
__global__ void __launch_bounds__(512, 1)
gemm_kernel(const float* __restrict__ x, float* __restrict__ out){
    extern __shared__ uint32_t smu[];
    uint32_t* xbuf = smu;              // 2 x [16][XSTR]
    uint32_t* wres = smu + 2*XBUF;     // [128][WSTR]

    const int tid  = threadIdx.x;
    const int lane = tid & 31;
    const int wid  = tid >> 5;
    const int g = lane >> 2, q = lane & 3;
    const int wp = wid >> 2, wc = wid & 3;
    const int bid = blockIdx.x;

    // ---- one-time W load: 16384 uint2 (128 k2-rows x 128 cout-pairs) ----
#pragma unroll
    for (int i = 0; i < 32; ++i){
        int id = tid + i * 512;            // 0..16383
        int k2 = id >> 7;                  // 0..127
        int n2 = (id & 127) << 1;
        const __half* r0 = g_wh + (size_t)(2 * k2) * CHANS + n2;
        uint32_t a = *(const uint32_t*)r0;
        uint32_t b = *(const uint32_t*)(r0 + CHANS);
        *(uint2*)(wres + k2 * WSTR + n2) =
            make_uint2(prmt(a, b, 0x5410), prmt(a, b, 0x7632));
    }

    const int ntiles = (NTILES - bid + NSM - 1) / NSM;   // 5 or 6
    const int gend   = ntiles * NCHUNK;

    // X staging coords: thread -> (k2 row, 4 consecutive pos); 4|3136 -> no straddle
    const int sk2 = tid >> 5;              // 0..15
    const int sp0 = (tid & 31) << 2;       // 0..124

    float4 xf0, xf1;
    auto ldg_x = [&](int gc){
        int t = gc >> 3, c = gc & 7;
        int tile = bid + t * NSM;
        int sn = tile * TILE_P + sp0;
        int b = sn / HWSZ, p = sn - b * HWSZ;
        const float* s0 = x + ((size_t)b * CHANS + (size_t)(c * KC + 2 * sk2)) * HWSZ + p;
        xf0 = *(const float4*)s0;
        xf1 = *(const float4*)(s0 + HWSZ);
    };
    auto sts_x = [&](uint32_t* buf){
        uint4 v;
        v.x = pkh2(xf1.x, xf0.x);  v.y = pkh2(xf1.y, xf0.y);
        v.z = pkh2(xf1.z, xf0.z);  v.w = pkh2(xf1.w, xf0.w);
        *(uint4*)(buf + sk2 * XSTR + sp0) = v;
    };

    float acc[2][8][4];
#pragma unroll
    for (int mt = 0; mt < 2; ++mt)
#pragma unroll
        for (int nt = 0; nt < 8; ++nt)
#pragma unroll
            for (int r = 0; r < 4; ++r) acc[mt][nt][r] = 0.f;

    // prologue: chunk0 into smem, chunk1 into regs (ntiles>=5 so gend>=40)
    ldg_x(0);
    sts_x(xbuf);
    ldg_x(1);
    __syncthreads();   // also covers resident-W visibility

    for (int gc = 0; gc < gend; ++gc){
        const uint32_t* xb = xbuf + (gc & 1) * XBUF;
        const uint32_t* wb = wres + (gc & 7) * 16 * WSTR;
#pragma unroll
        for (int ks = 0; ks < 2; ++ks){
            const uint32_t* xk = xb + (ks * 8 + q) * XSTR + wp * 32;
            uint32_t a[2][4];
#pragma unroll
            for (int mt = 0; mt < 2; ++mt){
                int p0 = mt * 16 + g;
                a[mt][0] = xk[p0];
                a[mt][1] = xk[p0 + 8];
                a[mt][2] = xk[4 * XSTR + p0];
                a[mt][3] = xk[4 * XSTR + p0 + 8];
            }
            const uint32_t* wk = wb + (ks * 8 + q) * WSTR + wc * 64 + g;
#pragma unroll
            for (int nt = 0; nt < 8; ++nt){
                uint32_t b0 = wk[nt * 8];
                uint32_t b1 = wk[4 * WSTR + nt * 8];
                mma16(acc[0][nt], a[0], b0, b1);
                mma16(acc[1][nt], a[1], b0, b1);
            }
        }

        // stage next chunk (single-sync safety: buffer (gc+1)&1 was last read
        // in iteration gc-1, fully fenced by the barrier at end of gc-1)
        const bool more = (gc + 1 < gend);
        if (more){
            sts_x(xbuf + ((gc + 1) & 1) * XBUF);
            if (gc + 2 < gend) ldg_x(gc + 2);
        }

        // per-tile epilogue (regs only; overlaps the in-flight LDGs)
        if ((gc & 7) == 7){
            int tile = bid + (gc >> 3) * NSM;
#pragma unroll
            for (int mt = 0; mt < 2; ++mt){
#pragma unroll
                for (int rs = 0; rs < 2; ++rs){
                    int pos = tile * TILE_P + wp * 32 + mt * 16 + g + rs * 8;
                    int b = pos / HWSZ, p = pos - b * HWSZ;
                    float* ob = out + ((size_t)b * CHANS + (size_t)(wc * 64 + 2 * q)) * HWSZ + p;
#pragma unroll
                    for (int nt = 0; nt < 8; ++nt){
                        ob[(size_t)(nt * 8) * HWSZ]     = acc[mt][nt][rs * 2 + 0];
                        ob[(size_t)(nt * 8 + 1) * HWSZ] = acc[mt][nt][rs * 2 + 1];
                    }
                }
            }
#pragma unroll
            for (int mt = 0; mt < 2; ++mt)
#pragma unroll
                for (int nt = 0; nt < 8; ++nt)
#pragma unroll
                    for (int r = 0; r < 4; ++r) acc[mt][nt][r] = 0.f;
        }

        if (more) __syncthreads();
    }
}

// ---------------- launch ----------------
extern "C" void kernel_launch(void* const* d_in, const int* in_sizes, int n_in,
                              void* d_out, int out_size)
{
    const float* acts = (const float*)d_in[0];
    const float* wrec = (const float*)d_in[1];
    float* out        = (float*)d_out;
    (void)in_sizes; (void)n_in; (void)out_size;

    cudaFuncSetAttribute(gemm_kernel, cudaFuncAttributeMaxDynamicSharedMemorySize, SMEM_BYTES);

    build_weff_kernel<<<CHANS, CHANS>>>(wrec);
    gemm_kernel<<<NSM, 512, SMEM_BYTES>>>(acts, out);
}